// round 5
// baseline (speedup 1.0000x reference)
#include <cuda_runtime.h>
#include <math.h>

#define MAXM 400000

// transposed scratch [row][M] (+pad so tail-block staging reads stay in bounds)
__device__ float g_taf_t[(size_t)51 * MAXM + 2048];
__device__ float g_tafm_t[(size_t)48 * MAXM + 2048];
__device__ float g_pf[MAXM + 1024];
__device__ float g_mf[MAXM + 1024];

typedef unsigned long long u64;

__device__ __forceinline__ u64 pack2(float lo, float hi) {
    u64 r; asm("mov.b64 %0,{%1,%2};" : "=l"(r) : "f"(lo), "f"(hi)); return r;
}
__device__ __forceinline__ void unpack2(u64 v, float& lo, float& hi) {
    asm("mov.b64 {%0,%1},%2;" : "=f"(lo), "=f"(hi) : "l"(v));
}
__device__ __forceinline__ void ffma2(u64& d, u64 a, u64 b) {
    asm("fma.rn.f32x2 %0,%1,%2,%0;" : "+l"(d) : "l"(a), "l"(b));
}
__device__ __forceinline__ float sigmoidf_(float x) { return 1.f / (1.f + expf(-x)); }

// ================= builder =================
__global__ __launch_bounds__(256)
void build_kernel(const float* __restrict__ cam,
                  const float* __restrict__ anchors,
                  const float* __restrict__ scales,
                  const float* __restrict__ afeat,
                  const float* __restrict__ tfeat,
                  const float* __restrict__ factors,
                  const int* __restrict__ vis,
                  const int* __restrict__ knn,
                  float* __restrict__ out, int M)
{
    int m = blockIdx.x * 256 + threadIdx.x;
    if (m >= M) return;
    int idx = vis[m];

    float a[51];
    const float4* fp = reinterpret_cast<const float4*>(afeat + (long long)idx * 32);
    #pragma unroll
    for (int q = 0; q < 8; q++) {
        float4 v = __ldg(fp + q);
        a[4*q+0] = v.x; a[4*q+1] = v.y; a[4*q+2] = v.z; a[4*q+3] = v.w;
    }
    float ax = __ldg(anchors + (long long)idx * 3 + 0);
    float ay = __ldg(anchors + (long long)idx * 3 + 1);
    float az = __ldg(anchors + (long long)idx * 3 + 2);
    float vx = ax - cam[3], vy = ay - cam[7], vz = az - cam[11];
    float nrm = sqrtf(vx*vx + vy*vy + vz*vz);
    float inv = 1.f / fmaxf(nrm, 1e-8f);
    a[32] = vx * inv; a[33] = vy * inv; a[34] = vz * inv;

    float4 fc = __ldg(reinterpret_cast<const float4*>(factors + (long long)idx * 4));
    float tff = fc.x, mf = fc.y, kf = fc.z, pf = fc.w;

    const float4* tp = reinterpret_cast<const float4*>(tfeat + (long long)idx * 256 + 112);
    #pragma unroll
    for (int q = 0; q < 4; q++) {
        float4 v = __ldg(tp + q);
        a[35+4*q+0] = v.x*tff; a[35+4*q+1] = v.y*tff;
        a[35+4*q+2] = v.z*tff; a[35+4*q+3] = v.w*tff;
    }

    #pragma unroll
    for (int i = 0; i < 51; i++)
        g_taf_t[(size_t)i * M + m] = a[i];
    g_pf[m] = pf;
    g_mf[m] = mf;

    float facc[48];
    #pragma unroll
    for (int i = 0; i < 48; i++) facc[i] = 0.f;
    const int* kp = knn + (long long)idx * 6;
    #pragma unroll 1
    for (int nb = 0; nb < 6; nb++) {
        int nidx = __ldg(kp + nb);
        const float4* nf = reinterpret_cast<const float4*>(afeat + (long long)nidx * 32);
        #pragma unroll
        for (int q = 0; q < 8; q++) {
            float4 v = __ldg(nf + q);
            facc[4*q+0] += v.x; facc[4*q+1] += v.y;
            facc[4*q+2] += v.z; facc[4*q+3] += v.w;
        }
        const float4* nt = reinterpret_cast<const float4*>(tfeat + (long long)nidx * 256 + 112);
        #pragma unroll
        for (int q = 0; q < 4; q++) {
            float4 v = __ldg(nt + q);
            facc[32+4*q+0] += v.x; facc[32+4*q+1] += v.y;
            facc[32+4*q+2] += v.z; facc[32+4*q+3] += v.w;
        }
    }
    float wk = (1.f - kf) * (1.f / 6.f);
    #pragma unroll
    for (int i = 0; i < 32; i++)
        g_tafm_t[(size_t)i * M + m] = kf * a[i] + wk * facc[i];
    #pragma unroll
    for (int c = 0; c < 16; c++)
        g_tafm_t[(size_t)(32 + c) * M + m] = kf * a[35 + c] + wk * facc[32 + c];

    float* om = out + (long long)M * 110 + (long long)m * 50;
    const float* sp = scales + (long long)idx * 6;
    om[37] = expf(__ldg(sp + 0));
    om[38] = expf(__ldg(sp + 1));
    om[39] = expf(__ldg(sp + 2));
    om[40] = expf(__ldg(sp + 3)) * pf;
    om[41] = expf(__ldg(sp + 4)) * pf;
    om[42] = expf(__ldg(sp + 5)) * pf;
    om[43] = tff; om[44] = mf; om[45] = kf; om[46] = pf;
    om[47] = ax; om[48] = ay; om[49] = az;
}

// ================= MLP body: 2 pts/thread, x+h in smem, h-pass fully on-chip =================
// smem: [W1: K*64][W2: 64*W2S][B1: 64][B2: W2S][XH: 64*512]
// ACT: 0=op(tanh*pf) 1=col(sigmoid) 2=cov(raw) 3=mot(*mf)
template <int K, int W2S, int NOUT, int ACT>
__device__ __forceinline__ void mlp_body(const float* __restrict__ xin,
                                         const float* __restrict__ w1g, const float* __restrict__ b1g,
                                         const float* __restrict__ w2g, const float* __restrict__ b2g,
                                         const float* __restrict__ scl,
                                         float* __restrict__ out, int M, float* S)
{
    constexpr int CH = 16;
    constexpr int NPASS = W2S / CH;
    constexpr int OW1 = 0;
    constexpr int OW2 = K * 64;
    constexpr int OB1 = OW2 + 64 * W2S;
    constexpr int OB2 = OB1 + 64;
    constexpr int OXH = OB2 + W2S;

    const int tid = threadIdx.x;

    // ---- stage weights ----
    for (int i = tid; i < K * 64; i += 256) S[OW1 + i] = w1g[i];
    for (int i = tid; i < 64 * W2S; i += 256) {
        int j = i / W2S, k = i - j * W2S;
        S[OW2 + i] = (k < NOUT) ? w2g[j * NOUT + k] : 0.f;
    }
    if (tid < 64) {
        float acc = b1g[tid];
        if (ACT == 3) {
            #pragma unroll
            for (int t = 0; t < 8; t++) {
                float ang = exp2f((float)t) * 1.5707963267948966f;
                acc = fmaf(sinf(ang), w1g[(48 + t) * 64 + tid], acc);
                acc = fmaf(cosf(ang), w1g[(56 + t) * 64 + tid], acc);
            }
        }
        S[OB1 + tid] = acc;
    }
    if (tid < W2S) S[OB2 + tid] = (tid < NOUT) ? b2g[tid] : 0.f;

    // ---- stage x tile (coalesced) ----
    const size_t bm0 = (size_t)blockIdx.x * 512;
    for (int t = tid; t < K * 512; t += 256) {
        int row = t >> 9, col = t & 511;
        S[OXH + t] = __ldg(xin + (size_t)row * M + bm0 + col);
    }
    __syncthreads();

    // ---- layer1: single 64-neuron chunk, acc = h (2 pts × 32 u64) ----
    u64 a0[32], a1[32];
    #pragma unroll
    for (int q = 0; q < 32; q++) {
        u64 b = *reinterpret_cast<const u64*>(S + OB1 + 2 * q);
        a0[q] = b; a1[q] = b;
    }
    #pragma unroll 3
    for (int i = 0; i < K; i++) {
        float2 x2 = *reinterpret_cast<const float2*>(S + OXH + i * 512 + 2 * tid);
        u64 xa = pack2(x2.x, x2.x), xb = pack2(x2.y, x2.y);
        const ulonglong2* wp = reinterpret_cast<const ulonglong2*>(S + OW1 + i * 64);
        #pragma unroll
        for (int q = 0; q < 16; q++) {
            ulonglong2 w = wp[q];
            ffma2(a0[2*q+0], xa, w.x); ffma2(a0[2*q+1], xa, w.y);
            ffma2(a1[2*q+0], xb, w.x); ffma2(a1[2*q+1], xb, w.y);
        }
    }
    // relu -> h into smem (same-thread columns of the XH region; per-column
    // ownership means no cross-thread hazard, no sync needed)
    #pragma unroll
    for (int q = 0; q < 32; q++) {
        float l, h;
        unpack2(a0[q], l, h);
        S[OXH + (2*q+0) * 512 + 2*tid] = fmaxf(l, 0.f);
        S[OXH + (2*q+1) * 512 + 2*tid] = fmaxf(h, 0.f);
        unpack2(a1[q], l, h);
        S[OXH + (2*q+0) * 512 + 2*tid + 1] = fmaxf(l, 0.f);
        S[OXH + (2*q+1) * 512 + 2*tid + 1] = fmaxf(h, 0.f);
    }

    const size_t m0 = bm0 + 2 * tid;

    // ---- layer2: NPASS passes of 16 outputs, h from smem (rolled j-loop) ----
    #pragma unroll 1
    for (int pass = 0; pass < NPASS; pass++) {
        const int k0 = pass * CH;
        u64 c0[8], c1[8];
        #pragma unroll
        for (int q = 0; q < 8; q++) {
            u64 b = *reinterpret_cast<const u64*>(S + OB2 + k0 + 2 * q);
            c0[q] = b; c1[q] = b;
        }
        #pragma unroll 4
        for (int j = 0; j < 64; j++) {
            float2 h2 = *reinterpret_cast<const float2*>(S + OXH + j * 512 + 2 * tid);
            u64 ha = pack2(h2.x, h2.x), hb = pack2(h2.y, h2.y);
            const ulonglong2* wr = reinterpret_cast<const ulonglong2*>(S + OW2 + j * W2S + k0);
            #pragma unroll
            for (int q = 0; q < 4; q++) {
                ulonglong2 w = wr[q];
                ffma2(c0[2*q+0], ha, w.x); ffma2(c0[2*q+1], ha, w.y);
                ffma2(c1[2*q+0], hb, w.x); ffma2(c1[2*q+1], hb, w.y);
            }
        }
        // scatter both points
        #pragma unroll
        for (int p = 0; p < 2; p++) {
            size_t m = m0 + p;
            if (m >= (size_t)M) break;
            float ov[16];
            #pragma unroll
            for (int q = 0; q < 8; q++)
                unpack2(p == 0 ? c0[q] : c1[q], ov[2*q], ov[2*q+1]);

            if (ACT == 0) {
                float pf = scl[m];
                float* omk = out + m * 110;
                #pragma unroll
                for (int k = 0; k < 16; k++)
                    if (k < 10) omk[k * 11] = tanhf(ov[k]) * pf;
            } else if (ACT == 1) {
                float* omk = out + m * 110;
                #pragma unroll
                for (int kk = 0; kk < 16; kk++) {
                    int k = k0 + kk;
                    if (k < 30) {
                        int kd = k / 3;
                        omk[kd * 11 + 1 + (k - kd * 3)] = sigmoidf_(ov[kk]);
                    }
                }
            } else if (ACT == 2) {
                float* omk = out + m * 110;
                #pragma unroll
                for (int kk = 0; kk < 16; kk++) {
                    int k = k0 + kk;
                    if (k < 70) {
                        int kd = k / 7;
                        omk[kd * 11 + 4 + (k - kd * 7)] = ov[kk];
                    }
                }
            } else {
                float mf = scl[m];
                float* om = out + (size_t)M * 110 + m * 50;
                #pragma unroll
                for (int kk = 0; kk < 16; kk++) {
                    int k = k0 + kk;
                    if (k < 37) om[k] = ov[kk] * mf;
                }
            }
        }
    }
}

// ================= merged 4-MLP dispatcher =================
__global__ __launch_bounds__(256, 1)
void mlp4_kernel(const float* __restrict__ taf, const float* __restrict__ tafm,
                 const float* __restrict__ op_w1,  const float* __restrict__ op_b1,
                 const float* __restrict__ op_w2,  const float* __restrict__ op_b2,
                 const float* __restrict__ col_w1, const float* __restrict__ col_b1,
                 const float* __restrict__ col_w2, const float* __restrict__ col_b2,
                 const float* __restrict__ cov_w1, const float* __restrict__ cov_b1,
                 const float* __restrict__ cov_w2, const float* __restrict__ cov_b2,
                 const float* __restrict__ mot_w1, const float* __restrict__ mot_b1,
                 const float* __restrict__ mot_w2, const float* __restrict__ mot_b2,
                 const float* __restrict__ pf, const float* __restrict__ mf,
                 float* __restrict__ out, int M)
{
    extern __shared__ float S[];
    switch (blockIdx.y) {
        case 0: mlp_body<51, 16, 10, 0>(taf,  op_w1,  op_b1,  op_w2,  op_b2,  pf, out, M, S); break;
        case 1: mlp_body<51, 32, 30, 1>(taf,  col_w1, col_b1, col_w2, col_b2, pf, out, M, S); break;
        case 2: mlp_body<51, 80, 70, 2>(taf,  cov_w1, cov_b1, cov_w2, cov_b2, pf, out, M, S); break;
        default: mlp_body<48, 48, 37, 3>(tafm, mot_w1, mot_b1, mot_w2, mot_b2, mf, out, M, S); break;
    }
}

// ================= launch =================
extern "C" void kernel_launch(void* const* d_in, const int* in_sizes, int n_in,
                              void* d_out, int out_size)
{
    const float* cam     = (const float*)d_in[0];
    const float* anchors = (const float*)d_in[1];
    const float* scales  = (const float*)d_in[2];
    const float* afeat   = (const float*)d_in[3];
    const float* tfeat   = (const float*)d_in[4];
    const float* factors = (const float*)d_in[5];
    const float* op_w1   = (const float*)d_in[6];
    const float* op_b1   = (const float*)d_in[7];
    const float* op_w2   = (const float*)d_in[8];
    const float* op_b2   = (const float*)d_in[9];
    const float* col_w1  = (const float*)d_in[10];
    const float* col_b1  = (const float*)d_in[11];
    const float* col_w2  = (const float*)d_in[12];
    const float* col_b2  = (const float*)d_in[13];
    const float* cov_w1  = (const float*)d_in[14];
    const float* cov_b1  = (const float*)d_in[15];
    const float* cov_w2  = (const float*)d_in[16];
    const float* cov_b2  = (const float*)d_in[17];
    const float* mot_w1  = (const float*)d_in[18];
    const float* mot_b1  = (const float*)d_in[19];
    const float* mot_w2  = (const float*)d_in[20];
    const float* mot_b2  = (const float*)d_in[21];
    const int*   vis     = (const int*)d_in[22];
    const int*   knn     = (const int*)d_in[23];

    int M = in_sizes[22];
    float* out = (float*)d_out;

    float *taf, *tafm, *pf, *mf;
    cudaGetSymbolAddress((void**)&taf,  g_taf_t);
    cudaGetSymbolAddress((void**)&tafm, g_tafm_t);
    cudaGetSymbolAddress((void**)&pf,   g_pf);
    cudaGetSymbolAddress((void**)&mf,   g_mf);

    const int GB = (M + 255) / 256;
    const int GX = (M + 511) / 512;

    // cov is largest: 51*64 + 64*80 + 64 + 80 + 64*512 = 41296 floats
    const int SMEM = 41296 * 4;
    cudaFuncSetAttribute(mlp4_kernel, cudaFuncAttributeMaxDynamicSharedMemorySize, SMEM);

    build_kernel<<<GB, 256>>>(cam, anchors, scales, afeat, tfeat, factors, vis, knn, out, M);
    mlp4_kernel<<<dim3(GX, 4), 256, SMEM>>>(
        taf, tafm,
        op_w1, op_b1, op_w2, op_b2,
        col_w1, col_b1, col_w2, col_b2,
        cov_w1, cov_b1, cov_w2, cov_b2,
        mot_w1, mot_b1, mot_w2, mot_b2,
        pf, mf, out, M);
}

// round 6
// speedup vs baseline: 1.1336x; 1.1336x over previous
#include <cuda_runtime.h>
#include <math.h>

#define MAXM 400000

// transposed scratch [row][M] (+pad so tail-block staging reads stay in bounds)
__device__ float g_taf_t[(size_t)51 * MAXM + 2048];
__device__ float g_tafm_t[(size_t)48 * MAXM + 2048];
__device__ float g_pf[MAXM + 1024];
__device__ float g_mf[MAXM + 1024];

typedef unsigned long long u64;

__device__ __forceinline__ u64 pack2(float lo, float hi) {
    u64 r; asm("mov.b64 %0,{%1,%2};" : "=l"(r) : "f"(lo), "f"(hi)); return r;
}
__device__ __forceinline__ void unpack2(u64 v, float& lo, float& hi) {
    asm("mov.b64 {%0,%1},%2;" : "=f"(lo), "=f"(hi) : "l"(v));
}
__device__ __forceinline__ void ffma2(u64& d, u64 a, u64 b) {
    asm("fma.rn.f32x2 %0,%1,%2,%0;" : "+l"(d) : "l"(a), "l"(b));
}
__device__ __forceinline__ float sigmoidf_(float x) { return 1.f / (1.f + expf(-x)); }

// ================= builder =================
__global__ __launch_bounds__(256)
void build_kernel(const float* __restrict__ cam,
                  const float* __restrict__ anchors,
                  const float* __restrict__ scales,
                  const float* __restrict__ afeat,
                  const float* __restrict__ tfeat,
                  const float* __restrict__ factors,
                  const int* __restrict__ vis,
                  const int* __restrict__ knn,
                  float* __restrict__ out, int M)
{
    int m = blockIdx.x * 256 + threadIdx.x;
    if (m >= M) return;
    int idx = vis[m];

    float a[51];
    const float4* fp = reinterpret_cast<const float4*>(afeat + (long long)idx * 32);
    #pragma unroll
    for (int q = 0; q < 8; q++) {
        float4 v = __ldg(fp + q);
        a[4*q+0] = v.x; a[4*q+1] = v.y; a[4*q+2] = v.z; a[4*q+3] = v.w;
    }
    float ax = __ldg(anchors + (long long)idx * 3 + 0);
    float ay = __ldg(anchors + (long long)idx * 3 + 1);
    float az = __ldg(anchors + (long long)idx * 3 + 2);
    float vx = ax - cam[3], vy = ay - cam[7], vz = az - cam[11];
    float nrm = sqrtf(vx*vx + vy*vy + vz*vz);
    float inv = 1.f / fmaxf(nrm, 1e-8f);
    a[32] = vx * inv; a[33] = vy * inv; a[34] = vz * inv;

    float4 fc = __ldg(reinterpret_cast<const float4*>(factors + (long long)idx * 4));
    float tff = fc.x, mf = fc.y, kf = fc.z, pf = fc.w;

    const float4* tp = reinterpret_cast<const float4*>(tfeat + (long long)idx * 256 + 112);
    #pragma unroll
    for (int q = 0; q < 4; q++) {
        float4 v = __ldg(tp + q);
        a[35+4*q+0] = v.x*tff; a[35+4*q+1] = v.y*tff;
        a[35+4*q+2] = v.z*tff; a[35+4*q+3] = v.w*tff;
    }

    #pragma unroll
    for (int i = 0; i < 51; i++)
        g_taf_t[(size_t)i * M + m] = a[i];
    g_pf[m] = pf;
    g_mf[m] = mf;

    float facc[48];
    #pragma unroll
    for (int i = 0; i < 48; i++) facc[i] = 0.f;
    const int* kp = knn + (long long)idx * 6;
    #pragma unroll 1
    for (int nb = 0; nb < 6; nb++) {
        int nidx = __ldg(kp + nb);
        const float4* nf = reinterpret_cast<const float4*>(afeat + (long long)nidx * 32);
        #pragma unroll
        for (int q = 0; q < 8; q++) {
            float4 v = __ldg(nf + q);
            facc[4*q+0] += v.x; facc[4*q+1] += v.y;
            facc[4*q+2] += v.z; facc[4*q+3] += v.w;
        }
        const float4* nt = reinterpret_cast<const float4*>(tfeat + (long long)nidx * 256 + 112);
        #pragma unroll
        for (int q = 0; q < 4; q++) {
            float4 v = __ldg(nt + q);
            facc[32+4*q+0] += v.x; facc[32+4*q+1] += v.y;
            facc[32+4*q+2] += v.z; facc[32+4*q+3] += v.w;
        }
    }
    float wk = (1.f - kf) * (1.f / 6.f);
    #pragma unroll
    for (int i = 0; i < 32; i++)
        g_tafm_t[(size_t)i * M + m] = kf * a[i] + wk * facc[i];
    #pragma unroll
    for (int c = 0; c < 16; c++)
        g_tafm_t[(size_t)(32 + c) * M + m] = kf * a[35 + c] + wk * facc[32 + c];

    float* om = out + (long long)M * 110 + (long long)m * 50;
    const float* sp = scales + (long long)idx * 6;
    om[37] = expf(__ldg(sp + 0));
    om[38] = expf(__ldg(sp + 1));
    om[39] = expf(__ldg(sp + 2));
    om[40] = expf(__ldg(sp + 3)) * pf;
    om[41] = expf(__ldg(sp + 4)) * pf;
    om[42] = expf(__ldg(sp + 5)) * pf;
    om[43] = tff; om[44] = mf; om[45] = kf; om[46] = pf;
    om[47] = ax; om[48] = ay; om[49] = az;
}

// ================= MLP kernel: 1 pt/thread, 256-pt tile, all on-chip =================
// smem: [W1: K*64][W2: 64*W2S][B1: 64][B2: W2S][XH: 64*256]
// ACT: 0=op(tanh*pf) 1=col(sigmoid) 2=cov(raw) 3=mot(*mf)
template <int K, int W2S, int NOUT, int CH, int ACT>
__global__ __launch_bounds__(256, 2)
void mlp_kernel(const float* __restrict__ xin,
                const float* __restrict__ w1g, const float* __restrict__ b1g,
                const float* __restrict__ w2g, const float* __restrict__ b2g,
                const float* __restrict__ scl,
                float* __restrict__ out, int M)
{
    constexpr int NPASS = W2S / CH;
    constexpr int NP = CH / 2;
    constexpr int OW1 = 0;
    constexpr int OW2 = K * 64;
    constexpr int OB1 = OW2 + 64 * W2S;
    constexpr int OB2 = OB1 + 64;
    constexpr int OXH = OB2 + W2S;   // W2S multiple of 4 -> 16B aligned

    extern __shared__ float S[];
    const int tid = threadIdx.x;

    // ---- stage weights ----
    for (int i = tid; i < K * 64; i += 256) S[OW1 + i] = w1g[i];
    for (int i = tid; i < 64 * W2S; i += 256) {
        int j = i / W2S, k = i - j * W2S;
        S[OW2 + i] = (k < NOUT) ? w2g[j * NOUT + k] : 0.f;
    }
    if (tid < 64) {
        float acc = b1g[tid];
        if (ACT == 3) {
            #pragma unroll
            for (int t = 0; t < 8; t++) {
                float ang = exp2f((float)t) * 1.5707963267948966f;
                acc = fmaf(sinf(ang), w1g[(48 + t) * 64 + tid], acc);
                acc = fmaf(cosf(ang), w1g[(56 + t) * 64 + tid], acc);
            }
        }
        S[OB1 + tid] = acc;
    }
    if (tid < W2S) S[OB2 + tid] = (tid < NOUT) ? b2g[tid] : 0.f;

    // ---- stage x tile (coalesced float4 loads) ----
    const size_t bm0 = (size_t)blockIdx.x * 256;
    for (int t = tid; t < K * 64; t += 256) {
        int row = t >> 6, c4 = (t & 63) << 2;
        float4 v = __ldg(reinterpret_cast<const float4*>(xin + (size_t)row * M + bm0 + c4));
        S[OXH + row * 256 + c4 + 0] = v.x;
        S[OXH + row * 256 + c4 + 1] = v.y;
        S[OXH + row * 256 + c4 + 2] = v.z;
        S[OXH + row * 256 + c4 + 3] = v.w;
    }
    __syncthreads();

    // ---- layer1: 64 neurons, 32 u64 accumulators, x read once per row ----
    u64 acc[32];
    #pragma unroll
    for (int q = 0; q < 32; q++)
        acc[q] = *reinterpret_cast<const u64*>(S + OB1 + 2 * q);
    #pragma unroll 2
    for (int i = 0; i < K; i++) {
        float x = S[OXH + i * 256 + tid];
        u64 xp = pack2(x, x);
        const ulonglong2* wp = reinterpret_cast<const ulonglong2*>(S + OW1 + i * 64);
        #pragma unroll
        for (int q = 0; q < 16; q++) {
            ulonglong2 w = wp[q];
            ffma2(acc[2*q+0], xp, w.x);
            ffma2(acc[2*q+1], xp, w.y);
        }
    }
    // relu -> h overwrites this thread's XH column (x fully consumed; column-private)
    #pragma unroll
    for (int q = 0; q < 32; q++) {
        float l, h; unpack2(acc[q], l, h);
        S[OXH + (2*q+0) * 256 + tid] = fmaxf(l, 0.f);
        S[OXH + (2*q+1) * 256 + tid] = fmaxf(h, 0.f);
    }

    const size_t m = bm0 + tid;
    const bool valid = (m < (size_t)M);
    float sv = valid ? scl[m] : 0.f;

    // ---- layer2: NPASS passes of CH outputs ----
    #pragma unroll 1
    for (int pass = 0; pass < NPASS; pass++) {
        const int k0 = pass * CH;
        u64 c[NP];
        #pragma unroll
        for (int q = 0; q < NP; q++)
            c[q] = *reinterpret_cast<const u64*>(S + OB2 + k0 + 2 * q);
        #pragma unroll 4
        for (int j = 0; j < 64; j++) {
            float hj = S[OXH + j * 256 + tid];
            u64 hp = pack2(hj, hj);
            const ulonglong2* wr = reinterpret_cast<const ulonglong2*>(S + OW2 + j * W2S + k0);
            #pragma unroll
            for (int q = 0; q < NP / 2; q++) {
                ulonglong2 w = wr[q];
                ffma2(c[2*q+0], hp, w.x);
                ffma2(c[2*q+1], hp, w.y);
            }
        }
        if (!valid) continue;
        float ov[CH];
        #pragma unroll
        for (int q = 0; q < NP; q++) unpack2(c[q], ov[2*q], ov[2*q+1]);

        if (ACT == 0) {
            float* omk = out + m * 110;
            #pragma unroll
            for (int k = 0; k < CH; k++)
                if (k < 10) omk[k * 11] = tanhf(ov[k]) * sv;
        } else if (ACT == 1) {
            float* omk = out + m * 110;
            #pragma unroll
            for (int k = 0; k < CH; k++)
                if (k < 30) {
                    int kd = k / 3;
                    omk[kd * 11 + 1 + (k - kd * 3)] = sigmoidf_(ov[k]);
                }
        } else if (ACT == 2) {
            float* omk = out + m * 110;
            #pragma unroll
            for (int kk = 0; kk < CH; kk++) {
                int k = k0 + kk;
                if (k < 70) {
                    int kd = k / 7;
                    omk[kd * 11 + 4 + (k - kd * 7)] = ov[kk];
                }
            }
        } else {
            float* om = out + (size_t)M * 110 + m * 50;
            #pragma unroll
            for (int kk = 0; kk < CH; kk++) {
                int k = k0 + kk;
                if (k < 37) om[k] = ov[kk] * sv;
            }
        }
    }
}

// ================= launch =================
extern "C" void kernel_launch(void* const* d_in, const int* in_sizes, int n_in,
                              void* d_out, int out_size)
{
    const float* cam     = (const float*)d_in[0];
    const float* anchors = (const float*)d_in[1];
    const float* scales  = (const float*)d_in[2];
    const float* afeat   = (const float*)d_in[3];
    const float* tfeat   = (const float*)d_in[4];
    const float* factors = (const float*)d_in[5];
    const float* op_w1   = (const float*)d_in[6];
    const float* op_b1   = (const float*)d_in[7];
    const float* op_w2   = (const float*)d_in[8];
    const float* op_b2   = (const float*)d_in[9];
    const float* col_w1  = (const float*)d_in[10];
    const float* col_b1  = (const float*)d_in[11];
    const float* col_w2  = (const float*)d_in[12];
    const float* col_b2  = (const float*)d_in[13];
    const float* cov_w1  = (const float*)d_in[14];
    const float* cov_b1  = (const float*)d_in[15];
    const float* cov_w2  = (const float*)d_in[16];
    const float* cov_b2  = (const float*)d_in[17];
    const float* mot_w1  = (const float*)d_in[18];
    const float* mot_b1  = (const float*)d_in[19];
    const float* mot_w2  = (const float*)d_in[20];
    const float* mot_b2  = (const float*)d_in[21];
    const int*   vis     = (const int*)d_in[22];
    const int*   knn     = (const int*)d_in[23];

    int M = in_sizes[22];
    float* out = (float*)d_out;

    float *taf, *tafm, *pf, *mf;
    cudaGetSymbolAddress((void**)&taf,  g_taf_t);
    cudaGetSymbolAddress((void**)&tafm, g_tafm_t);
    cudaGetSymbolAddress((void**)&pf,   g_pf);
    cudaGetSymbolAddress((void**)&mf,   g_mf);

    const int GB = (M + 255) / 256;
    const int GM = (M + 255) / 256;

    auto smem_bytes = [](int K, int W2S) {
        return (K * 64 + 64 * W2S + 64 + W2S + 64 * 256) * 4;
    };
    int smem_op  = smem_bytes(51, 16);
    int smem_col = smem_bytes(51, 32);
    int smem_cov = smem_bytes(51, 72);
    int smem_mot = smem_bytes(48, 40);

    cudaFuncSetAttribute((const void*)mlp_kernel<51,16,10,16,0>, cudaFuncAttributeMaxDynamicSharedMemorySize, smem_op);
    cudaFuncSetAttribute((const void*)mlp_kernel<51,32,30,32,1>, cudaFuncAttributeMaxDynamicSharedMemorySize, smem_col);
    cudaFuncSetAttribute((const void*)mlp_kernel<51,72,70,24,2>, cudaFuncAttributeMaxDynamicSharedMemorySize, smem_cov);
    cudaFuncSetAttribute((const void*)mlp_kernel<48,40,37,20,3>, cudaFuncAttributeMaxDynamicSharedMemorySize, smem_mot);

    build_kernel<<<GB, 256>>>(cam, anchors, scales, afeat, tfeat, factors, vis, knn, out, M);
    mlp_kernel<51,16,10,16,0><<<GM, 256, smem_op >>>(taf,  op_w1,  op_b1,  op_w2,  op_b2,  pf, out, M);
    mlp_kernel<51,32,30,32,1><<<GM, 256, smem_col>>>(taf,  col_w1, col_b1, col_w2, col_b2, pf, out, M);
    mlp_kernel<51,72,70,24,2><<<GM, 256, smem_cov>>>(taf,  cov_w1, cov_b1, cov_w2, cov_b2, pf, out, M);
    mlp_kernel<48,40,37,20,3><<<GM, 256, smem_mot>>>(tafm, mot_w1, mot_b1, mot_w2, mot_b2, mf, out, M);
}